// round 11
// baseline (speedup 1.0000x reference)
#include <cuda_runtime.h>
#include <cuda_bf16.h>
#include <math.h>
#include <stdint.h>

#define Bq 64
#define Tq 32
#define Eq 512
#define Hq 512
#define H4 2048
#define Vq 10000

// ---------------- scratch (static device globals; no allocation) ----------------
__device__ __nv_bfloat16 g_xs_h[Tq * Bq * Eq];    // xs split hi   2MB
__device__ __nv_bfloat16 g_xs_l[Tq * Bq * Eq];    // xs split lo   2MB
__device__ __nv_bfloat16 g_wih_h[H4 * Eq];        // W_ih split    2MB
__device__ __nv_bfloat16 g_wih_l[H4 * Eq];
__device__ __nv_bfloat16 g_fcw_h[Vq * Hq];        // fc_W split   10MB
__device__ __nv_bfloat16 g_fcw_l[Vq * Hq];
__device__ __nv_bfloat16 g_hs_h[Tq * Bq * Hq];    // h_seq split   2MB
__device__ __nv_bfloat16 g_hs_l[Tq * Bq * Hq];
__device__ float g_xproj[Tq * Bq * H4];           // [T][B][4H]   16MB
__device__ float g_bias[H4];                      // b_ih + b_hh
__device__ int   g_tok[Bq * Tq];                  // decoded caption tokens
__device__ unsigned g_cnt;                        // grid barrier counter
__device__ volatile unsigned g_gen;               // grid barrier generation

// ---------------- helpers -------------------------------------------------------
__device__ __forceinline__ uint32_t smem_u32(const void* p) {
    uint32_t a;
    asm("{ .reg .u64 t; cvta.to.shared.u64 t, %1; cvt.u32.u64 %0, t; }" : "=r"(a) : "l"(p));
    return a;
}

#define LDSM4(r, addr) \
    asm volatile("ldmatrix.sync.aligned.m8n8.x4.shared.b16 {%0,%1,%2,%3}, [%4];" \
        : "=r"((r)[0]), "=r"((r)[1]), "=r"((r)[2]), "=r"((r)[3]) : "r"(addr))

#define MMA16816(d, a, b) \
    asm volatile("mma.sync.aligned.m16n8k16.row.col.f32.bf16.bf16.f32 " \
        "{%0,%1,%2,%3}, {%4,%5,%6,%7}, {%8,%9}, {%0,%1,%2,%3};" \
        : "+f"((d)[0]), "+f"((d)[1]), "+f"((d)[2]), "+f"((d)[3]) \
        : "r"((a)[0]), "r"((a)[1]), "r"((a)[2]), "r"((a)[3]), "r"((b)[0]), "r"((b)[1]))

__device__ __forceinline__ void split1(float x, __nv_bfloat16& h, __nv_bfloat16& l) {
    h = __float2bfloat16(x);
    l = __float2bfloat16(x - __bfloat162float(h));
}

// ---------------- token decode: handle captions as int32 OR int64 ---------------
__global__ void k_tok(const int* __restrict__ cap32) {
    __shared__ int s_or;
    if (threadIdx.x == 0) s_or = 0;
    __syncthreads();
    int tid = threadIdx.x;                 // 1024 threads
    if (cap32[2 * tid + 1] != 0) atomicOr(&s_or, 1);
    __syncthreads();
    bool is64 = (s_or == 0);
    for (int i = tid; i < Bq * Tq; i += 1024) {
        int tok = is64 ? cap32[2 * i] : cap32[i];
        tok = tok < 0 ? 0 : (tok >= Vq ? Vq - 1 : tok);
        g_tok[i] = tok;
    }
}

// ---------------- prep: gather embeddings (split to bf16 hi/lo), bias, barrier --
__global__ void k_prep(const float* __restrict__ feat,
                       const float* __restrict__ embW,
                       const float* __restrict__ b_ih,
                       const float* __restrict__ b_hh) {
    int i = blockIdx.x * blockDim.x + threadIdx.x;   // 262144: one float4 of xs each
    int e4 = i & 127;            // E/4 = 128
    int b  = (i >> 7) & 63;
    int t  = i >> 13;
    float4 v;
    if (t == 0) {
        v = ((const float4*)feat)[b * 128 + e4];
    } else {
        int tok = g_tok[b * Tq + t];
        v = ((const float4*)embW)[(size_t)tok * 128 + e4];
    }
    __nv_bfloat16 h0, l0, h1, l1, h2, l2, h3, l3;
    split1(v.x, h0, l0); split1(v.y, h1, l1);
    split1(v.z, h2, l2); split1(v.w, h3, l3);
    ((ushort4*)g_xs_h)[i] = make_ushort4(__bfloat16_as_ushort(h0), __bfloat16_as_ushort(h1),
                                         __bfloat16_as_ushort(h2), __bfloat16_as_ushort(h3));
    ((ushort4*)g_xs_l)[i] = make_ushort4(__bfloat16_as_ushort(l0), __bfloat16_as_ushort(l1),
                                         __bfloat16_as_ushort(l2), __bfloat16_as_ushort(l3));

    if (i < H4) g_bias[i] = b_ih[i] + b_hh[i];
    if (i == 0) { g_cnt = 0; g_gen = 0; }
}

// ---------------- generic fp32 -> bf16 hi/lo split -------------------------------
__global__ void k_split(const float* __restrict__ in, __nv_bfloat16* __restrict__ oh,
                        __nv_bfloat16* __restrict__ ol, int n4) {
    int i = blockIdx.x * blockDim.x + threadIdx.x;
    if (i >= n4) return;
    float4 v = ((const float4*)in)[i];
    __nv_bfloat16 h0, l0, h1, l1, h2, l2, h3, l3;
    split1(v.x, h0, l0); split1(v.y, h1, l1);
    split1(v.z, h2, l2); split1(v.w, h3, l3);
    ((ushort4*)oh)[i] = make_ushort4(__bfloat16_as_ushort(h0), __bfloat16_as_ushort(h1),
                                     __bfloat16_as_ushort(h2), __bfloat16_as_ushort(h3));
    ((ushort4*)ol)[i] = make_ushort4(__bfloat16_as_ushort(l0), __bfloat16_as_ushort(l1),
                                     __bfloat16_as_ushort(l2), __bfloat16_as_ushort(l3));
}

// ---------------- HMMA bf16 3-pass GEMM: C = A*B^T + bias -----------------------
// Block tile 128x128, BK=32, 8 warps of 32m x 64n. cp.async double-buffered smem,
// XOR-16B swizzle, ldmatrix.x4 fragments, mma.sync.m16n8k16.
// Register-lean schedule (B-lo loaded after hi passes) -> fits 2 CTAs/SM.
// MODE 0: C[m*2048 + n]                          (x_proj)
// MODE 1: out[(m&63)*T*V + (m>>6)*V + n], n<Nn   (fc logits scatter to [B][T][V])
#define TILE_A_H 0
#define TILE_A_L 8192
#define TILE_B_H 16384
#define TILE_B_L 24576
#define BUF_STRIDE 32768
#define SMEM_TOTAL 65536
#define NKB 16

template <int MODE>
__global__ void __launch_bounds__(256, 2)
k_mma(const __nv_bfloat16* __restrict__ Ah, const __nv_bfloat16* __restrict__ Al,
      const __nv_bfloat16* __restrict__ Bh, const __nv_bfloat16* __restrict__ Bl,
      const float* __restrict__ bias, float* __restrict__ C, int Nn) {
    extern __shared__ char smem[];
    const uint32_t sb = smem_u32(smem);
    const int tid  = threadIdx.x;
    const int lane = tid & 31;
    const int wid  = tid >> 5;
    const int bm = blockIdx.y * 128;
    const int bn = blockIdx.x * 128;
    const int m0 = (wid & 3) * 32;     // warp m-offset within tile
    const int n0 = (wid >> 2) * 64;    // warp n-offset within tile

    float acc[2][8][4];
    #pragma unroll
    for (int ma = 0; ma < 2; ma++)
        #pragma unroll
        for (int na = 0; na < 8; na++)
            #pragma unroll
            for (int q = 0; q < 4; q++) acc[ma][na][q] = 0.f;

    auto fill = [&](int kb, int buf) {
        #pragma unroll
        for (int i = 0; i < 8; i++) {
            int q = tid + i * 256;           // 0..2047 chunk id
            int tile = q >> 9;               // 0..3 (Ah, Al, Bh, Bl)
            int w = q & 511;
            int row = w >> 2, c = w & 3;
            uint32_t dst = sb + (uint32_t)buf * BUF_STRIDE + (uint32_t)tile * 8192
                         + (uint32_t)(row * 64) + (uint32_t)((c ^ (row & 3)) << 4);
            int kc = kb * 32 + c * 8;
            const __nv_bfloat16* src;
            bool valid = true;
            if (tile == 0)      src = Ah + (size_t)(bm + row) * 512 + kc;
            else if (tile == 1) src = Al + (size_t)(bm + row) * 512 + kc;
            else {
                valid = (MODE == 0) || (bn + row) < Nn;
                src = (tile == 2 ? Bh : Bl) + (size_t)(bn + row) * 512 + kc;
            }
            if (valid)
                asm volatile("cp.async.cg.shared.global [%0], [%1], 16;"
                             :: "r"(dst), "l"(src));
            else
                asm volatile("st.shared.v4.b32 [%0], {%1,%1,%1,%1};" :: "r"(dst), "r"(0u));
        }
    };

    auto compute = [&](int buf) {
        const uint32_t bb = sb + (uint32_t)buf * BUF_STRIDE;
        #pragma unroll
        for (int ka = 0; ka < 2; ka++) {
            // A fragments (hi+lo) stay resident for all three passes
            uint32_t ahf[2][4], alf[2][4];
            const int arow0 = m0 + (lane & 15);
            const int ack = ka * 2 + (lane >> 4);
            #pragma unroll
            for (int ma = 0; ma < 2; ma++) {
                int row = arow0 + ma * 16;
                uint32_t off = (uint32_t)(row * 64) + (uint32_t)((ack ^ (row & 3)) << 4);
                LDSM4(ahf[ma], bb + TILE_A_H + off);
                LDSM4(alf[ma], bb + TILE_A_L + off);
            }
            const int brow0 = n0 + (lane & 7) + ((lane >> 4) & 1) * 8;
            const int bck = ka * 2 + ((lane >> 3) & 1);
            // phase 1: B-hi resident -> hi*hi and lo*hi passes
            {
                uint32_t bf[8][2];
                #pragma unroll
                for (int g = 0; g < 4; g++) {
                    int row = brow0 + g * 16;
                    uint32_t off = (uint32_t)(row * 64) + (uint32_t)((bck ^ (row & 3)) << 4);
                    uint32_t r[4];
                    LDSM4(r, bb + TILE_B_H + off);
                    bf[2*g][0] = r[0]; bf[2*g][1] = r[1];
                    bf[2*g+1][0] = r[2]; bf[2*g+1][1] = r[3];
                }
                #pragma unroll
                for (int ma = 0; ma < 2; ma++)
                    #pragma unroll
                    for (int na = 0; na < 8; na++) {
                        MMA16816(acc[ma][na], ahf[ma], bf[na]);   // hi*hi
                        MMA16816(acc[ma][na], alf[ma], bf[na]);   // lo*hi
                    }
            }
            // phase 2: B-lo (reuses dead B-hi registers) -> hi*lo pass
            {
                uint32_t bf[8][2];
                #pragma unroll
                for (int g = 0; g < 4; g++) {
                    int row = brow0 + g * 16;
                    uint32_t off = (uint32_t)(row * 64) + (uint32_t)((bck ^ (row & 3)) << 4);
                    uint32_t r[4];
                    LDSM4(r, bb + TILE_B_L + off);
                    bf[2*g][0] = r[0]; bf[2*g][1] = r[1];
                    bf[2*g+1][0] = r[2]; bf[2*g+1][1] = r[3];
                }
                #pragma unroll
                for (int ma = 0; ma < 2; ma++)
                    #pragma unroll
                    for (int na = 0; na < 8; na++)
                        MMA16816(acc[ma][na], ahf[ma], bf[na]);   // hi*lo
            }
        }
    };

    fill(0, 0);
    asm volatile("cp.async.commit_group;" ::: "memory");
    for (int kb = 0; kb < NKB; kb++) {
        if (kb + 1 < NKB) {
            fill(kb + 1, (kb + 1) & 1);
            asm volatile("cp.async.commit_group;" ::: "memory");
            asm volatile("cp.async.wait_group 1;" ::: "memory");
        } else {
            asm volatile("cp.async.wait_group 0;" ::: "memory");
        }
        __syncthreads();
        compute(kb & 1);
        __syncthreads();
    }

    #pragma unroll
    for (int ma = 0; ma < 2; ma++)
        #pragma unroll
        for (int na = 0; na < 8; na++) {
            int mrow0 = bm + m0 + ma * 16 + (lane >> 2);
            int n = bn + n0 + na * 8 + (lane & 3) * 2;
            if (MODE == 1 && n >= Nn) continue;
            float2 bv = *(const float2*)(bias + n);
            #pragma unroll
            for (int half = 0; half < 2; half++) {
                int m = mrow0 + half * 8;
                size_t base = (MODE == 0)
                    ? (size_t)m * 2048 + n
                    : (size_t)(m & 63) * (Tq * (size_t)Vq) + (size_t)(m >> 6) * Vq + n;
                float2 o;
                o.x = acc[ma][na][half * 2 + 0] + bv.x;
                o.y = acc[ma][na][half * 2 + 1] + bv.y;
                *(float2*)(C + base) = o;
            }
        }
}

// ---------------- persistent tensor-core LSTM scan (64 fat blocks) --------------
// 64 blocks x 256 threads (8 warps). Block owns 8 j-columns x 4 gates = 32 W rows,
// split to bf16 hi/lo ONCE in smem. Warp w: m-atom ma=w>>1 (16 batches), j-half
// h=w&1 (W rows 16h..16h+15 = natoms 2h,2h+1). Per step: stage h(t-1) hi/lo via
// cp.async, 3-pass HMMA, shfl gate exchange (verified round-9 mapping), update.
// smem: A_hi[0,64K) A_lo[64K,128K) W_hi[128K,160K) W_lo[160K,192K)
#define SC_A_L   65536
#define SC_W_H   131072
#define SC_W_L   163840
#define SC_SMEM  196608
#define SC_BLK   64

__device__ __forceinline__ void gridsync(unsigned gen) {
    __syncthreads();
    if (threadIdx.x == 0) {
        __threadfence();
        if (atomicAdd(&g_cnt, 1) == (SC_BLK - 1)) {
            g_cnt = 0;
            __threadfence();
            g_gen = gen;
        } else {
            while (g_gen != gen) __nanosleep(32);
            __threadfence();
        }
    }
    __syncthreads();
}

__global__ void __launch_bounds__(256, 1) k_scan(const float* __restrict__ Whh) {
    extern __shared__ char smem[];
    const uint32_t sb = smem_u32(smem);
    const int tid  = threadIdx.x;
    const int lane = tid & 31;
    const int w    = tid >> 5;          // warp 0..7
    const int ma   = w >> 1;            // m-atom: batches 16ma..16ma+15
    const int hh_  = w & 1;             // j-half: W rows 16h..16h+15
    const int j0   = blockIdx.x * 8;

    // ---- load + split W_hh slice (32 rows x 512) into smem once.
    // row r (0..31): h=r>>4, rr=r&15, g=rr>>2, jl=h*4+(rr&3); Whh row = g*512+j0+jl
    for (int idx = tid; idx < 32 * 512; idx += 256) {
        int r = idx >> 9, k = idx & 511;
        int rr = r & 15;
        int grow = (rr >> 2) * Hq + j0 + (r >> 4) * 4 + (rr & 3);
        float wv = Whh[(size_t)grow * Hq + k];
        __nv_bfloat16 wh, wl;
        split1(wv, wh, wl);
        int kb = k >> 5, c = (k >> 3) & 3, e = k & 7;
        uint32_t off = (uint32_t)(kb * 2048 + r * 64 + ((c ^ (r & 3)) << 4) + e * 2);
        *(__nv_bfloat16*)(smem + SC_W_H + off) = wh;
        *(__nv_bfloat16*)(smem + SC_W_L + off) = wl;
    }
    __syncthreads();

    // ---- static epilogue mapping per lane (round-9 verified)
    const int type = lane & 3;
    const int own  = (type >= 2) ? 1 : 0;        // own acc column within pair
    const int snd  = 1 - own;
    const int jm   = (type & 1) * 2 + own;       // my j within the half's 4
    const int jg   = j0 + hh_ * 4 + jm;          // global j
    const int b0   = ma * 16 + (lane >> 2);      // my two batches: b0, b0+8

    float c0 = 0.f, c1 = 0.f;                    // cell state for (b0, jg), (b0+8, jg)

    for (int t = 0; t < Tq; t++) {
        float acc[2][4];
        #pragma unroll
        for (int na = 0; na < 2; na++)
            #pragma unroll
            for (int q = 0; q < 4; q++) acc[na][q] = 0.f;

        if (t > 0) {
            // stage h(t-1) hi/lo: 8192 16B chunks, 32 per thread
            const __nv_bfloat16* hsh = g_hs_h + (size_t)(t - 1) * Bq * Hq;
            const __nv_bfloat16* hsl = g_hs_l + (size_t)(t - 1) * Bq * Hq;
            #pragma unroll
            for (int i = 0; i < 32; i++) {
                int q = tid + i * 256;           // 0..8191
                int sel = q >> 12;               // 0 = hi, 1 = lo
                int v = q & 4095;
                int row = v >> 6, kb = (v >> 2) & 15, c = v & 3;
                uint32_t dst = sb + (uint32_t)sel * SC_A_L
                             + (uint32_t)(kb * 4096 + row * 64 + ((c ^ (row & 3)) << 4));
                const __nv_bfloat16* src = (sel ? hsl : hsh) + row * 512 + kb * 32 + c * 8;
                asm volatile("cp.async.cg.shared.global [%0], [%1], 16;"
                             :: "r"(dst), "l"(src));
            }
            asm volatile("cp.async.commit_group;" ::: "memory");
            asm volatile("cp.async.wait_group 0;" ::: "memory");
            __syncthreads();

            // 3-pass MMA: warp tile m16(batches) x n16(2 natoms) x K=512
            const int arow = ma * 16 + (lane & 15);
            const int brow = hh_ * 16 + (lane & 7) + ((lane >> 4) & 1) * 8;
            #pragma unroll 4
            for (int kb = 0; kb < 16; kb++) {
                #pragma unroll
                for (int ka = 0; ka < 2; ka++) {
                    const int ack = ka * 2 + (lane >> 4);
                    const int bck = ka * 2 + ((lane >> 3) & 1);
                    uint32_t aoff = (uint32_t)(kb * 4096 + arow * 64 + ((ack ^ (arow & 3)) << 4));
                    uint32_t boff = (uint32_t)(kb * 2048 + brow * 64 + ((bck ^ (brow & 3)) << 4));
                    uint32_t ahf[4], alf[4], bh4[4], bl4[4];
                    LDSM4(ahf, sb + aoff);
                    LDSM4(alf, sb + SC_A_L + aoff);
                    LDSM4(bh4, sb + SC_W_H + boff);
                    LDSM4(bl4, sb + SC_W_L + boff);
                    uint32_t bh0[2] = {bh4[0], bh4[1]}, bh1[2] = {bh4[2], bh4[3]};
                    uint32_t bl0[2] = {bl4[0], bl4[1]}, bl1[2] = {bl4[2], bl4[3]};
                    MMA16816(acc[0], ahf, bh0);
                    MMA16816(acc[0], ahf, bl0);
                    MMA16816(acc[0], alf, bh0);
                    MMA16816(acc[1], ahf, bh1);
                    MMA16816(acc[1], ahf, bl1);
                    MMA16816(acc[1], alf, bh1);
                }
            }
        }

        // ---- gate exchange: pair lanes l <-> l^2 hold complementary gates
        const float* xp = g_xproj + (size_t)t * Bq * H4;
        float* csel[2] = {&c0, &c1};
        #pragma unroll
        for (int half = 0; half < 2; half++) {
            int b = b0 + half * 8;
            float o0 = acc[0][half * 2 + own];   // my gate (g0 or g1) at my j
            float o1 = acc[1][half * 2 + own];   // my gate (g2 or g3) at my j
            float s0 = acc[0][half * 2 + snd];   // partner's j, my gates
            float s1 = acc[1][half * 2 + snd];
            float r0 = __shfl_xor_sync(0xFFFFFFFF, s0, 2);
            float r1 = __shfl_xor_sync(0xFFFFFFFF, s1, 2);
            float gi = (type < 2 ? o0 : r0);
            float gf = (type < 2 ? r0 : o0);
            float gg = (type < 2 ? o1 : r1);
            float go = (type < 2 ? r1 : o1);
            const float* xpb = xp + (size_t)b * H4 + jg;
            gi += __ldg(xpb);
            gf += __ldg(xpb + 512);
            gg += __ldg(xpb + 1024);
            go += __ldg(xpb + 1536);
            float si = 1.f / (1.f + __expf(-gi));
            float sf = 1.f / (1.f + __expf(-gf));
            float so = 1.f / (1.f + __expf(-go));
            float cn = sf * (*csel[half]) + si * tanhf(gg);
            *csel[half] = cn;
            float hn = so * tanhf(cn);
            __nv_bfloat16 hhv, hlv;
            split1(hn, hhv, hlv);
            size_t mi = (size_t)(t * Bq + b) * Hq + jg;
            g_hs_h[mi] = hhv;
            g_hs_l[mi] = hlv;
        }
        if (t < Tq - 1) gridsync((unsigned)(t + 1));
    }
}

// ---------------- launch --------------------------------------------------------
extern "C" void kernel_launch(void* const* d_in, const int* in_sizes, int n_in,
                              void* d_out, int out_size) {
    const float* feat = (const float*)d_in[0];
    const int*   cap  = (const int*)d_in[1];     // int32 OR int64 — detected on device
    const float* embW = (const float*)d_in[2];
    const float* W_ih = (const float*)d_in[3];
    const float* W_hh = (const float*)d_in[4];
    const float* b_ih = (const float*)d_in[5];
    const float* b_hh = (const float*)d_in[6];
    const float* fc_W = (const float*)d_in[7];
    const float* fc_b = (const float*)d_in[8];
    float* out = (float*)d_out;

    static int smem_set = 0;
    if (!smem_set) {
        cudaFuncSetAttribute(k_mma<0>, cudaFuncAttributeMaxDynamicSharedMemorySize, SMEM_TOTAL);
        cudaFuncSetAttribute(k_mma<1>, cudaFuncAttributeMaxDynamicSharedMemorySize, SMEM_TOTAL);
        cudaFuncSetAttribute(k_scan,   cudaFuncAttributeMaxDynamicSharedMemorySize, SC_SMEM);
        smem_set = 1;
    }

    __nv_bfloat16 *p_xs_h, *p_xs_l, *p_wih_h, *p_wih_l, *p_fcw_h, *p_fcw_l, *p_hs_h, *p_hs_l;
    float *p_xproj, *p_bias;
    cudaGetSymbolAddress((void**)&p_xs_h,  g_xs_h);
    cudaGetSymbolAddress((void**)&p_xs_l,  g_xs_l);
    cudaGetSymbolAddress((void**)&p_wih_h, g_wih_h);
    cudaGetSymbolAddress((void**)&p_wih_l, g_wih_l);
    cudaGetSymbolAddress((void**)&p_fcw_h, g_fcw_h);
    cudaGetSymbolAddress((void**)&p_fcw_l, g_fcw_l);
    cudaGetSymbolAddress((void**)&p_hs_h,  g_hs_h);
    cudaGetSymbolAddress((void**)&p_hs_l,  g_hs_l);
    cudaGetSymbolAddress((void**)&p_xproj, g_xproj);
    cudaGetSymbolAddress((void**)&p_bias,  g_bias);

    // order chosen so the profiler's fixed capture slot (4th launch) hits k_mma<0>
    k_tok<<<1, 1024>>>(cap);                                         // 1
    k_prep<<<1024, 256>>>(feat, embW, b_ih, b_hh);                   // 2
    k_split<<<1024, 256>>>(W_ih, p_wih_h, p_wih_l, H4 * Eq / 4);     // 3
    k_mma<0><<<dim3(16, 16), 256, SMEM_TOTAL>>>(p_xs_h, p_xs_l, p_wih_h, p_wih_l,
                                                p_bias, p_xproj, H4);// 4
    k_split<<<5000, 256>>>(fc_W, p_fcw_h, p_fcw_l, Vq * Hq / 4);     // 5
    k_scan<<<SC_BLK, 256, SC_SMEM>>>(W_hh);                          // 6
    k_mma<1><<<dim3((Vq + 127) / 128, 16), 256, SMEM_TOTAL>>>(p_hs_h, p_hs_l, p_fcw_h, p_fcw_l,
                                                              fc_b, out, Vq);  // 7
}

// round 14
// speedup vs baseline: 1.1319x; 1.1319x over previous
#include <cuda_runtime.h>
#include <cuda_bf16.h>
#include <math.h>
#include <stdint.h>

#define Bq 64
#define Tq 32
#define Eq 512
#define Hq 512
#define H4 2048
#define Vq 10000

// ---------------- scratch (static device globals; no allocation) ----------------
__device__ __nv_bfloat16 g_xs_h[Tq * Bq * Eq];    // xs split hi   2MB
__device__ __nv_bfloat16 g_xs_l[Tq * Bq * Eq];    // xs split lo   2MB
__device__ __nv_bfloat16 g_wih_h[H4 * Eq];        // W_ih split    2MB
__device__ __nv_bfloat16 g_wih_l[H4 * Eq];
__device__ __nv_bfloat16 g_fcw_h[Vq * Hq];        // fc_W split   10MB
__device__ __nv_bfloat16 g_fcw_l[Vq * Hq];
__device__ __nv_bfloat16 g_hs_h[Tq * Bq * Hq];    // h_seq split   2MB
__device__ __nv_bfloat16 g_hs_l[Tq * Bq * Hq];
__device__ float g_xproj[Tq * Bq * H4];           // [T][B][4H]   16MB
__device__ float g_bias[H4];                      // b_ih + b_hh
__device__ int   g_tok[Bq * Tq];                  // decoded caption tokens
__device__ unsigned g_cnt;                        // grid barrier counter
__device__ volatile unsigned g_gen;               // grid barrier generation

// ---------------- helpers -------------------------------------------------------
__device__ __forceinline__ uint32_t smem_u32(const void* p) {
    uint32_t a;
    asm("{ .reg .u64 t; cvta.to.shared.u64 t, %1; cvt.u32.u64 %0, t; }" : "=r"(a) : "l"(p));
    return a;
}

#define LDSM4(r, addr) \
    asm volatile("ldmatrix.sync.aligned.m8n8.x4.shared.b16 {%0,%1,%2,%3}, [%4];" \
        : "=r"((r)[0]), "=r"((r)[1]), "=r"((r)[2]), "=r"((r)[3]) : "r"(addr))

#define MMA16816(d, a, b) \
    asm volatile("mma.sync.aligned.m16n8k16.row.col.f32.bf16.bf16.f32 " \
        "{%0,%1,%2,%3}, {%4,%5,%6,%7}, {%8,%9}, {%0,%1,%2,%3};" \
        : "+f"((d)[0]), "+f"((d)[1]), "+f"((d)[2]), "+f"((d)[3]) \
        : "r"((a)[0]), "r"((a)[1]), "r"((a)[2]), "r"((a)[3]), "r"((b)[0]), "r"((b)[1]))

__device__ __forceinline__ void split1(float x, __nv_bfloat16& h, __nv_bfloat16& l) {
    h = __float2bfloat16(x);
    l = __float2bfloat16(x - __bfloat162float(h));
}

// ---------------- token decode: handle captions as int32 OR int64 ---------------
__global__ void k_tok(const int* __restrict__ cap32) {
    __shared__ int s_or;
    if (threadIdx.x == 0) s_or = 0;
    __syncthreads();
    int tid = threadIdx.x;                 // 1024 threads
    if (cap32[2 * tid + 1] != 0) atomicOr(&s_or, 1);
    __syncthreads();
    bool is64 = (s_or == 0);
    for (int i = tid; i < Bq * Tq; i += 1024) {
        int tok = is64 ? cap32[2 * i] : cap32[i];
        tok = tok < 0 ? 0 : (tok >= Vq ? Vq - 1 : tok);
        g_tok[i] = tok;
    }
}

// ---------------- prep: gather embeddings (split to bf16 hi/lo), bias, barrier --
__global__ void k_prep(const float* __restrict__ feat,
                       const float* __restrict__ embW,
                       const float* __restrict__ b_ih,
                       const float* __restrict__ b_hh) {
    int i = blockIdx.x * blockDim.x + threadIdx.x;   // 262144: one float4 of xs each
    int e4 = i & 127;            // E/4 = 128
    int b  = (i >> 7) & 63;
    int t  = i >> 13;
    float4 v;
    if (t == 0) {
        v = ((const float4*)feat)[b * 128 + e4];
    } else {
        int tok = g_tok[b * Tq + t];
        v = ((const float4*)embW)[(size_t)tok * 128 + e4];
    }
    __nv_bfloat16 h0, l0, h1, l1, h2, l2, h3, l3;
    split1(v.x, h0, l0); split1(v.y, h1, l1);
    split1(v.z, h2, l2); split1(v.w, h3, l3);
    ((ushort4*)g_xs_h)[i] = make_ushort4(__bfloat16_as_ushort(h0), __bfloat16_as_ushort(h1),
                                         __bfloat16_as_ushort(h2), __bfloat16_as_ushort(h3));
    ((ushort4*)g_xs_l)[i] = make_ushort4(__bfloat16_as_ushort(l0), __bfloat16_as_ushort(l1),
                                         __bfloat16_as_ushort(l2), __bfloat16_as_ushort(l3));

    if (i < H4) g_bias[i] = b_ih[i] + b_hh[i];
    if (i == 0) { g_cnt = 0; g_gen = 0; }
}

// ---------------- generic fp32 -> bf16 hi/lo split -------------------------------
__global__ void k_split(const float* __restrict__ in, __nv_bfloat16* __restrict__ oh,
                        __nv_bfloat16* __restrict__ ol, int n4) {
    int i = blockIdx.x * blockDim.x + threadIdx.x;
    if (i >= n4) return;
    float4 v = ((const float4*)in)[i];
    __nv_bfloat16 h0, l0, h1, l1, h2, l2, h3, l3;
    split1(v.x, h0, l0); split1(v.y, h1, l1);
    split1(v.z, h2, l2); split1(v.w, h3, l3);
    ((ushort4*)oh)[i] = make_ushort4(__bfloat16_as_ushort(h0), __bfloat16_as_ushort(h1),
                                     __bfloat16_as_ushort(h2), __bfloat16_as_ushort(h3));
    ((ushort4*)ol)[i] = make_ushort4(__bfloat16_as_ushort(l0), __bfloat16_as_ushort(l1),
                                     __bfloat16_as_ushort(l2), __bfloat16_as_ushort(l3));
}

// ---------------- HMMA bf16 3-pass GEMM: C = A*B^T + bias -----------------------
// Block tile 128x128, BK=32, 8 warps of 32m x 64n. 3-stage cp.async pipeline
// (ONE __syncthreads per k-block), XOR-16B swizzle, ldmatrix.x4, mma.m16n8k16.
// Register-lean schedule (B-lo loaded after hi passes) -> 2 CTAs/SM.
// MODE 0: C[m*2048 + n]                          (x_proj)
// MODE 1: out[(m&63)*T*V + (m>>6)*V + n], n<Nn   (fc logits scatter to [B][T][V])
#define TILE_A_H 0
#define TILE_A_L 8192
#define TILE_B_H 16384
#define TILE_B_L 24576
#define BUF_STRIDE 32768
#define SMEM_TOTAL (3 * 32768)
#define NKB 16

template <int MODE>
__global__ void __launch_bounds__(256, 2)
k_mma(const __nv_bfloat16* __restrict__ Ah, const __nv_bfloat16* __restrict__ Al,
      const __nv_bfloat16* __restrict__ Bh, const __nv_bfloat16* __restrict__ Bl,
      const float* __restrict__ bias, float* __restrict__ C, int Nn) {
    extern __shared__ char smem[];
    const uint32_t sb = smem_u32(smem);
    const int tid  = threadIdx.x;
    const int lane = tid & 31;
    const int wid  = tid >> 5;
    const int bm = blockIdx.y * 128;
    const int bn = blockIdx.x * 128;
    const int m0 = (wid & 3) * 32;     // warp m-offset within tile
    const int n0 = (wid >> 2) * 64;    // warp n-offset within tile

    float acc[2][8][4];
    #pragma unroll
    for (int ma = 0; ma < 2; ma++)
        #pragma unroll
        for (int na = 0; na < 8; na++)
            #pragma unroll
            for (int q = 0; q < 4; q++) acc[ma][na][q] = 0.f;

    auto fill = [&](int kb) {
        const int buf = kb % 3;
        #pragma unroll
        for (int i = 0; i < 8; i++) {
            int q = tid + i * 256;           // 0..2047 chunk id
            int tile = q >> 9;               // 0..3 (Ah, Al, Bh, Bl)
            int w = q & 511;
            int row = w >> 2, c = w & 3;
            uint32_t dst = sb + (uint32_t)buf * BUF_STRIDE + (uint32_t)tile * 8192
                         + (uint32_t)(row * 64) + (uint32_t)((c ^ (row & 3)) << 4);
            int kc = kb * 32 + c * 8;
            const __nv_bfloat16* src;
            bool valid = true;
            if (tile == 0)      src = Ah + (size_t)(bm + row) * 512 + kc;
            else if (tile == 1) src = Al + (size_t)(bm + row) * 512 + kc;
            else {
                valid = (MODE == 0) || (bn + row) < Nn;
                src = (tile == 2 ? Bh : Bl) + (size_t)(bn + row) * 512 + kc;
            }
            if (valid)
                asm volatile("cp.async.cg.shared.global [%0], [%1], 16;"
                             :: "r"(dst), "l"(src));
            else
                asm volatile("st.shared.v4.b32 [%0], {%1,%1,%1,%1};" :: "r"(dst), "r"(0u));
        }
        asm volatile("cp.async.commit_group;" ::: "memory");
    };

    auto compute = [&](int kb) {
        const uint32_t bb = sb + (uint32_t)(kb % 3) * BUF_STRIDE;
        #pragma unroll
        for (int ka = 0; ka < 2; ka++) {
            // A fragments (hi+lo) stay resident for all three passes
            uint32_t ahf[2][4], alf[2][4];
            const int arow0 = m0 + (lane & 15);
            const int ack = ka * 2 + (lane >> 4);
            #pragma unroll
            for (int ma = 0; ma < 2; ma++) {
                int row = arow0 + ma * 16;
                uint32_t off = (uint32_t)(row * 64) + (uint32_t)((ack ^ (row & 3)) << 4);
                LDSM4(ahf[ma], bb + TILE_A_H + off);
                LDSM4(alf[ma], bb + TILE_A_L + off);
            }
            const int brow0 = n0 + (lane & 7) + ((lane >> 4) & 1) * 8;
            const int bck = ka * 2 + ((lane >> 3) & 1);
            // phase 1: B-hi resident -> hi*hi and lo*hi passes
            {
                uint32_t bf[8][2];
                #pragma unroll
                for (int g = 0; g < 4; g++) {
                    int row = brow0 + g * 16;
                    uint32_t off = (uint32_t)(row * 64) + (uint32_t)((bck ^ (row & 3)) << 4);
                    uint32_t r[4];
                    LDSM4(r, bb + TILE_B_H + off);
                    bf[2*g][0] = r[0]; bf[2*g][1] = r[1];
                    bf[2*g+1][0] = r[2]; bf[2*g+1][1] = r[3];
                }
                #pragma unroll
                for (int ma = 0; ma < 2; ma++)
                    #pragma unroll
                    for (int na = 0; na < 8; na++) {
                        MMA16816(acc[ma][na], ahf[ma], bf[na]);   // hi*hi
                        MMA16816(acc[ma][na], alf[ma], bf[na]);   // lo*hi
                    }
            }
            // phase 2: B-lo (reuses dead B-hi registers) -> hi*lo pass
            {
                uint32_t bf[8][2];
                #pragma unroll
                for (int g = 0; g < 4; g++) {
                    int row = brow0 + g * 16;
                    uint32_t off = (uint32_t)(row * 64) + (uint32_t)((bck ^ (row & 3)) << 4);
                    uint32_t r[4];
                    LDSM4(r, bb + TILE_B_L + off);
                    bf[2*g][0] = r[0]; bf[2*g][1] = r[1];
                    bf[2*g+1][0] = r[2]; bf[2*g+1][1] = r[3];
                }
                #pragma unroll
                for (int ma = 0; ma < 2; ma++)
                    #pragma unroll
                    for (int na = 0; na < 8; na++)
                        MMA16816(acc[ma][na], ahf[ma], bf[na]);   // hi*lo
            }
        }
    };

    // 3-stage pipeline, ONE barrier per k-block.
    fill(0);
    fill(1);
    for (int kb = 0; kb < NKB; kb++) {
        if (kb == NKB - 1)
            asm volatile("cp.async.wait_group 0;" ::: "memory");
        else
            asm volatile("cp.async.wait_group 1;" ::: "memory");
        __syncthreads();
        if (kb + 2 < NKB) fill(kb + 2);   // writes buf (kb+2)%3 = (kb-1)%3: safe post-barrier
        compute(kb);
    }

    #pragma unroll
    for (int ma = 0; ma < 2; ma++)
        #pragma unroll
        for (int na = 0; na < 8; na++) {
            int mrow0 = bm + m0 + ma * 16 + (lane >> 2);
            int n = bn + n0 + na * 8 + (lane & 3) * 2;
            if (MODE == 1 && n >= Nn) continue;
            float2 bv = *(const float2*)(bias + n);
            #pragma unroll
            for (int half = 0; half < 2; half++) {
                int m = mrow0 + half * 8;
                size_t base = (MODE == 0)
                    ? (size_t)m * 2048 + n
                    : (size_t)(m & 63) * (Tq * (size_t)Vq) + (size_t)(m >> 6) * Vq + n;
                float2 o;
                o.x = acc[ma][na][half * 2 + 0] + bv.x;
                o.y = acc[ma][na][half * 2 + 1] + bv.y;
                *(float2*)(C + base) = o;
            }
        }
}

// ---------------- persistent tensor-core LSTM scan (round-10 proven config) -----
// 128 blocks x 128 threads. Block owns 4 j-columns x 4 gates = 16 W_hh rows,
// split to bf16 hi/lo ONCE in smem. Per step: stage h(t-1) hi/lo (g_hs arrays)
// via cp.async, 3-pass HMMA (64x16x512), shfl gate exchange, elementwise update.
// smem: A_hi[64K) A_lo[64K,128K) W_hi[128K,144K) W_lo[144K,160K)
#define SC_A_L   65536
#define SC_W_H   131072
#define SC_W_L   147456
#define SC_SMEM  163840
#define SC_BLK   128

__device__ __forceinline__ void gridsync(unsigned gen) {
    __syncthreads();
    if (threadIdx.x == 0) {
        __threadfence();
        if (atomicAdd(&g_cnt, 1) == (SC_BLK - 1)) {
            g_cnt = 0;
            __threadfence();
            g_gen = gen;
        } else {
            while (g_gen != gen) __nanosleep(32);
            __threadfence();
        }
    }
    __syncthreads();
}

__global__ void __launch_bounds__(128, 1) k_scan(const float* __restrict__ Whh) {
    extern __shared__ char smem[];
    const uint32_t sb = smem_u32(smem);
    const int tid  = threadIdx.x;
    const int lane = tid & 31;
    const int w    = tid >> 5;          // warp 0..3 -> m-rows 16w..16w+15
    const int j0   = blockIdx.x * 4;

    // ---- load + split W_hh slice into smem (once). row = g*4+jl -> Whh row g*512+j0+jl
    for (int idx = tid; idx < 16 * 512; idx += 128) {
        int row = idx >> 9, k = idx & 511;
        int grow = (row >> 2) * Hq + j0 + (row & 3);
        float wv = Whh[(size_t)grow * Hq + k];
        __nv_bfloat16 wh, wl;
        split1(wv, wh, wl);
        int kb = k >> 5, c = (k >> 3) & 3, e = k & 7;
        uint32_t off = (uint32_t)(kb * 1024 + row * 64 + ((c ^ (row & 3)) << 4) + e * 2);
        *(__nv_bfloat16*)(smem + SC_W_H + off) = wh;
        *(__nv_bfloat16*)(smem + SC_W_L + off) = wl;
    }
    __syncthreads();

    // ---- static epilogue mapping per lane
    const int type = lane & 3;
    const int own  = (type >= 2) ? 1 : 0;        // own acc column within pair
    const int snd  = 1 - own;
    const int jm   = (type & 1) * 2 + own;       // my j within block's 4
    const int jg   = j0 + jm;                    // global j
    const int b0   = w * 16 + (lane >> 2);       // my two batches: b0, b0+8

    float c0 = 0.f, c1 = 0.f;                    // cell state for (b0, jg), (b0+8, jg)

    for (int t = 0; t < Tq; t++) {
        float acc[2][4];
        #pragma unroll
        for (int na = 0; na < 2; na++)
            #pragma unroll
            for (int q = 0; q < 4; q++) acc[na][q] = 0.f;

        if (t > 0) {
            // stage h(t-1) hi/lo: 8192 16B chunks, 64 per thread
            const __nv_bfloat16* hsh = g_hs_h + (size_t)(t - 1) * Bq * Hq;
            const __nv_bfloat16* hsl = g_hs_l + (size_t)(t - 1) * Bq * Hq;
            #pragma unroll
            for (int i = 0; i < 64; i++) {
                int q = tid + i * 128;           // 0..8191
                int sel = q >> 12;               // 0 = hi, 1 = lo
                int v = q & 4095;
                int row = v >> 6, kb = (v >> 2) & 15, c = v & 3;
                uint32_t dst = sb + (uint32_t)sel * SC_A_L
                             + (uint32_t)(kb * 4096 + row * 64 + ((c ^ (row & 3)) << 4));
                const __nv_bfloat16* src = (sel ? hsl : hsh) + row * 512 + kb * 32 + c * 8;
                asm volatile("cp.async.cg.shared.global [%0], [%1], 16;"
                             :: "r"(dst), "l"(src));
            }
            asm volatile("cp.async.commit_group;" ::: "memory");
            asm volatile("cp.async.wait_group 0;" ::: "memory");
            __syncthreads();

            // 3-pass MMA: M=64 (warp m16), N=16, K=512
            const int arow = w * 16 + (lane & 15);
            const int brow = (lane & 7) + ((lane >> 4) & 1) * 8;
            #pragma unroll 4
            for (int kb = 0; kb < 16; kb++) {
                #pragma unroll
                for (int ka = 0; ka < 2; ka++) {
                    const int ack = ka * 2 + (lane >> 4);
                    const int bck = ka * 2 + ((lane >> 3) & 1);
                    uint32_t aoff = (uint32_t)(kb * 4096 + arow * 64 + ((ack ^ (arow & 3)) << 4));
                    uint32_t boff = (uint32_t)(kb * 1024 + brow * 64 + ((bck ^ (brow & 3)) << 4));
                    uint32_t ahf[4], alf[4], bh4[4], bl4[4];
                    LDSM4(ahf, sb + aoff);
                    LDSM4(alf, sb + SC_A_L + aoff);
                    LDSM4(bh4, sb + SC_W_H + boff);
                    LDSM4(bl4, sb + SC_W_L + boff);
                    uint32_t bh0[2] = {bh4[0], bh4[1]}, bh1[2] = {bh4[2], bh4[3]};
                    uint32_t bl0[2] = {bl4[0], bl4[1]}, bl1[2] = {bl4[2], bl4[3]};
                    MMA16816(acc[0], ahf, bh0);
                    MMA16816(acc[0], ahf, bl0);
                    MMA16816(acc[0], alf, bh0);
                    MMA16816(acc[1], ahf, bh1);
                    MMA16816(acc[1], ahf, bl1);
                    MMA16816(acc[1], alf, bh1);
                }
            }
        }

        // ---- gate exchange: pair lanes l <-> l^2 hold complementary gates
        const float* xp = g_xproj + (size_t)t * Bq * H4;
        float* csel[2] = {&c0, &c1};
        #pragma unroll
        for (int half = 0; half < 2; half++) {
            int b = b0 + half * 8;
            float o0 = acc[0][half * 2 + own];   // my gate (g0 or g1) at my j
            float o1 = acc[1][half * 2 + own];   // my gate (g2 or g3) at my j
            float s0 = acc[0][half * 2 + snd];   // partner's j, my gates
            float s1 = acc[1][half * 2 + snd];
            float r0 = __shfl_xor_sync(0xFFFFFFFF, s0, 2);
            float r1 = __shfl_xor_sync(0xFFFFFFFF, s1, 2);
            float gi = (type < 2 ? o0 : r0);
            float gf = (type < 2 ? r0 : o0);
            float gg = (type < 2 ? o1 : r1);
            float go = (type < 2 ? r1 : o1);
            const float* xpb = xp + (size_t)b * H4 + jg;
            gi += __ldg(xpb);
            gf += __ldg(xpb + 512);
            gg += __ldg(xpb + 1024);
            go += __ldg(xpb + 1536);
            float si = 1.f / (1.f + __expf(-gi));
            float sf = 1.f / (1.f + __expf(-gf));
            float so = 1.f / (1.f + __expf(-go));
            float cn = sf * (*csel[half]) + si * tanhf(gg);
            *csel[half] = cn;
            float hn = so * tanhf(cn);
            __nv_bfloat16 hh, hl;
            split1(hn, hh, hl);
            size_t mi = (size_t)(t * Bq + b) * Hq + jg;
            g_hs_h[mi] = hh;
            g_hs_l[mi] = hl;
        }
        if (t < Tq - 1) gridsync((unsigned)(t + 1));
    }
}

// ---------------- launch --------------------------------------------------------
extern "C" void kernel_launch(void* const* d_in, const int* in_sizes, int n_in,
                              void* d_out, int out_size) {
    const float* feat = (const float*)d_in[0];
    const int*   cap  = (const int*)d_in[1];     // int32 OR int64 — detected on device
    const float* embW = (const float*)d_in[2];
    const float* W_ih = (const float*)d_in[3];
    const float* W_hh = (const float*)d_in[4];
    const float* b_ih = (const float*)d_in[5];
    const float* b_hh = (const float*)d_in[6];
    const float* fc_W = (const float*)d_in[7];
    const float* fc_b = (const float*)d_in[8];
    float* out = (float*)d_out;

    static int smem_set = 0;
    if (!smem_set) {
        cudaFuncSetAttribute(k_mma<0>, cudaFuncAttributeMaxDynamicSharedMemorySize, SMEM_TOTAL);
        cudaFuncSetAttribute(k_mma<1>, cudaFuncAttributeMaxDynamicSharedMemorySize, SMEM_TOTAL);
        cudaFuncSetAttribute(k_scan,   cudaFuncAttributeMaxDynamicSharedMemorySize, SC_SMEM);
        smem_set = 1;
    }

    __nv_bfloat16 *p_xs_h, *p_xs_l, *p_wih_h, *p_wih_l, *p_fcw_h, *p_fcw_l, *p_hs_h, *p_hs_l;
    float *p_xproj, *p_bias;
    cudaGetSymbolAddress((void**)&p_xs_h,  g_xs_h);
    cudaGetSymbolAddress((void**)&p_xs_l,  g_xs_l);
    cudaGetSymbolAddress((void**)&p_wih_h, g_wih_h);
    cudaGetSymbolAddress((void**)&p_wih_l, g_wih_l);
    cudaGetSymbolAddress((void**)&p_fcw_h, g_fcw_h);
    cudaGetSymbolAddress((void**)&p_fcw_l, g_fcw_l);
    cudaGetSymbolAddress((void**)&p_hs_h,  g_hs_h);
    cudaGetSymbolAddress((void**)&p_hs_l,  g_hs_l);
    cudaGetSymbolAddress((void**)&p_xproj, g_xproj);
    cudaGetSymbolAddress((void**)&p_bias,  g_bias);

    // order chosen so the profiler's fixed capture slot (4th launch) hits k_mma<0>
    k_tok<<<1, 1024>>>(cap);                                         // 1
    k_prep<<<1024, 256>>>(feat, embW, b_ih, b_hh);                   // 2
    k_split<<<1024, 256>>>(W_ih, p_wih_h, p_wih_l, H4 * Eq / 4);     // 3
    k_mma<0><<<dim3(16, 16), 256, SMEM_TOTAL>>>(p_xs_h, p_xs_l, p_wih_h, p_wih_l,
                                                p_bias, p_xproj, H4);// 4
    k_split<<<5000, 256>>>(fc_W, p_fcw_h, p_fcw_l, Vq * Hq / 4);     // 5
    k_scan<<<SC_BLK, 128, SC_SMEM>>>(W_hh);                          // 6
    k_mma<1><<<dim3((Vq + 127) / 128, 16), 256, SMEM_TOTAL>>>(p_hs_h, p_hs_l, p_fcw_h, p_fcw_l,
                                                              fc_b, out, Vq);  // 7
}